// round 11
// baseline (speedup 1.0000x reference)
#include <cuda_runtime.h>

// ---------------------------------------------------------------------------
// DecGreenNet_product_CP3 — single fused 256-thread kernel, role-split blocks:
//   A (bid 0..767)    : branch partials over 32-node chunks
//   V (bid 768..895)  : reduce -> s_br -> rhs -> c ; 4 rows of v each
//   C (bid 896..1407) : out[i] = c + sum_h v[h] tanh(x_i.W[:,h]+b[h])
// All A+V resident in wave 1 (bid order) -> flag pipeline is deadlock-free.
// C hybrid tanh: even h MUFU tanh.approx (16 cyc), odd h fp32 Pade[7/6]
// on the FMA pipe (13 FMA + rcp) — cuts the MUFU ceiling 128->96 cyc/pair.
// ---------------------------------------------------------------------------

#define PI_F 3.14159265358979323846f
#define NA   768
#define NV   128
#define NCHUNK 256              // 8192/32 chunks per branch

__device__ float g_part[3][NCHUNK][128];
__device__ float g_party[3][NCHUNK];
__device__ float g_v[512];
__device__ float g_c;
__device__ int   g_cntA;
__device__ int   g_cntV;
__device__ int   g_flagV;
__device__ int   g_cntEnd;

__device__ __forceinline__ float tanh_mufu(float x) {
    float y;
    asm("tanh.approx.f32 %0, %1;" : "=f"(y) : "f"(x));
    return y;
}
__device__ __forceinline__ float frcp(float x) {
    float y;
    asm("rcp.approx.f32 %0, %1;" : "=f"(y) : "f"(x));
    return y;
}
// accurate tanh (~1e-6) for the branch path (cancellation-sensitive sums)
__device__ __forceinline__ float tanh_acc(float z) {
    float e = __expf(2.0f * z);
    return 1.0f - __fdividef(2.0f, e + 1.0f);
}
// fp32 Pade[7/6] tanh on FMA pipe, clamp +-4.97, abs err <= ~1e-4
__device__ __forceinline__ float tanh_fma(float z) {
    const float zc = fminf(fmaxf(z, -4.97f), 4.97f);
    const float t  = zc * zc;
    const float p  = zc * fmaf(t, fmaf(t, t + 378.0f, 17325.0f), 135135.0f);
    const float q  = fmaf(t, fmaf(t, fmaf(t, 28.0f, 3150.0f), 62370.0f), 135135.0f);
    return p * frcp(q);
}

__global__ void __launch_bounds__(256) mega(
        const float* __restrict__ X,
        const float* __restrict__ eq,
        const float* __restrict__ q0, const float* __restrict__ q1,
        const float* __restrict__ q2,
        const float* __restrict__ Wx1, const float* __restrict__ bx1,
        const float* __restrict__ Wx2, const float* __restrict__ bx2,
        const float* __restrict__ w0, const float* __restrict__ c0,
        const float* __restrict__ W02, const float* __restrict__ B02,
        const float* __restrict__ w1, const float* __restrict__ c1,
        const float* __restrict__ W12, const float* __restrict__ B12,
        const float* __restrict__ w2, const float* __restrict__ c2,
        const float* __restrict__ W22, const float* __restrict__ B22,
        float* __restrict__ out, int Bn)
{
    const int bid  = blockIdx.x;
    const int tid  = threadIdx.x;
    const int lane = tid & 31;
    const int w    = tid >> 5;        // 0..7

    // =================== A role: branch partials (32-node chunks) ========
    if (bid < NA) {
        const int br    = bid / NCHUNK;
        const int chunk = bid - br * NCHUNK;
        const float* qx = (br == 0) ? q0 : ((br == 1) ? q1 : q2);
        const float* W1 = (br == 0) ? w0 : ((br == 1) ? w1 : w2);
        const float* B1 = (br == 0) ? c0 : ((br == 1) ? c1 : c2);

        __shared__ float pacc[2][128];
        __shared__ float syp[2];

        const int grp = w >> 2;       // 0..1 -> which 16 nodes
        const int j   = ((w & 3) << 5) + lane;

        const float pe = PI_F * eq[0];
        float q = 0.f, y = 0.f;
        if (lane < 16) {
            q = qx[chunk * 32 + grp * 16 + lane];
            y = sinf(pe * q);
        }

        const float wj = W1[j];
        const float bj = B1[j];
        float acc0 = 0.f, acc1 = 0.f;     // 2 chains halve the serial depth
#pragma unroll
        for (int k = 0; k < 16; k += 2) {
            const float qa = __shfl_sync(0xffffffffu, q, k);
            const float ya = __shfl_sync(0xffffffffu, y, k);
            const float qb = __shfl_sync(0xffffffffu, q, k + 1);
            const float yb = __shfl_sync(0xffffffffu, y, k + 1);
            acc0 = fmaf(ya, tanh_acc(fmaf(qa, wj, bj)), acc0);
            acc1 = fmaf(yb, tanh_acc(fmaf(qb, wj, bj)), acc1);
        }
        pacc[grp][j] = acc0 + acc1;

        if ((w & 3) == 0 && lane < 16) {  // warps 0,4 reduce their 16 y's
            float s = y;
#pragma unroll
            for (int o = 8; o; o >>= 1) s += __shfl_xor_sync(0xffffu, s, o);
            if (lane == 0) syp[grp] = s;
        }
        __syncthreads();

        if (tid < 128) {
            g_part[br][chunk][tid] = pacc[0][tid] + pacc[1][tid];
        } else if (tid == 128) {
            g_party[br][chunk] = syp[0] + syp[1];
        }
        __syncthreads();
        __threadfence();
        if (tid == 0) atomicAdd(&g_cntA, 1);
    }
    // =================== V role: rhs + 4 rows of v =======================
    else if (bid < NA + NV) {
        const int vid = bid - NA;

        __shared__ float wh[3][128];
        __shared__ float sumy[3];
        __shared__ float s_sh[3][128];
        __shared__ __align__(16) float rsh[512];
        __shared__ float red[256];

        // L2-prefetch this block's 4 Wx2 rows while A runs (no regs held)
        {
            const float* base = Wx2 + (vid * 4) * 512;
            for (int off = tid * 32; off < 4 * 512; off += 256 * 32)
                asm volatile("prefetch.global.L2 [%0];" :: "l"(base + off));
        }
        if (tid == 0) {
            while (*(volatile int*)&g_cntA != NA) __nanosleep(64);
        }
        __syncthreads();
        __threadfence();

        // phase 1: wh (384 vals) + sumy (3) over 256 chunks
        {
            const int br = tid >> 7, j = tid & 127;    // items 0..255
            float a = 0.f;
#pragma unroll 16
            for (int blk = 0; blk < NCHUNK; blk++) a += g_part[br][blk][j];
            wh[br][j] = a;
        }
        if (tid < 128) {                               // items 256..383 (br=2)
            float a = 0.f;
#pragma unroll 16
            for (int blk = 0; blk < NCHUNK; blk++) a += g_part[2][blk][tid];
            wh[2][tid] = a;
        } else if (tid < 131) {
            const int br = tid - 128;
            float s = 0.f;
#pragma unroll 16
            for (int blk = 0; blk < NCHUNK; blk++) s += g_party[br][blk];
            sumy[br] = s;
        }
        __syncthreads();

        // phase 2: s_br = wh_br @ Wq2_br + sumy_br * bq2_br
        {
            const int br = tid >> 7, c = tid & 127;
            const float* W2 = (br == 0) ? W02 : W12;
            const float* B2 = (br == 0) ? B02 : B12;
            float a = sumy[br] * B2[c];
#pragma unroll 16
            for (int j = 0; j < 128; j++) a = fmaf(wh[br][j], W2[j * 128 + c], a);
            s_sh[br][c] = a;
        }
        if (tid < 128) {
            float a = sumy[2] * B22[tid];
#pragma unroll 16
            for (int j = 0; j < 128; j++) a = fmaf(wh[2][j], W22[j * 128 + tid], a);
            s_sh[2][tid] = a;
        }
        __syncthreads();

        // phase 3: rhs (512) + c
        float rc = 0.f;
#pragma unroll
        for (int half = 0; half < 2; half++) {
            const int k = tid + half * 256;
            const int b = k >> 6, d = (k >> 3) & 7, f = k & 7;
            float r = 0.f;
#pragma unroll
            for (int x = 0; x < 16; x++)
                r += s_sh[0][b * 16 + x] * s_sh[1][d * 16 + x] * s_sh[2][f * 16 + x];
            rsh[k] = r;
            rc = fmaf(bx2[k], r, rc);
        }
        red[tid] = rc;
        __syncthreads();
        for (int off = 128; off > 0; off >>= 1) {
            if (tid < off) red[tid] += red[tid + off];
            __syncthreads();
        }
        if (vid == 0 && tid == 0) g_c = red[0];

        // phase V: 4 rows, warp per row (warps 4..7 idle)
        if (w < 4) {
            const int h = vid * 4 + w;
            const float4* row4 = (const float4*)(Wx2 + h * 512);
            const float4* r4   = (const float4*)rsh;
            float a = 0.f;
#pragma unroll
            for (int k = lane; k < 128; k += 32) {
                const float4 wv = row4[k];
                const float4 rv = r4[k];
                a = fmaf(wv.x, rv.x, fmaf(wv.y, rv.y,
                    fmaf(wv.z, rv.z, fmaf(wv.w, rv.w, a))));
            }
#pragma unroll
            for (int o = 16; o; o >>= 1) a += __shfl_xor_sync(0xffffffffu, a, o);
            if (lane == 0) g_v[h] = a;
        }
        __syncthreads();
        __threadfence();
        if (tid == 0) {
            const int r = atomicAdd(&g_cntV, 1);
            if (r == NV - 1) atomicExch(&g_flagV, 1);
        }
    }
    // =================== C role: main batch ==============================
    else {
        const int cid = bid - (NA + NV);

        __shared__ float4 wt[512];
        __shared__ float  vs[512];
        __shared__ __align__(16) float pp[8][128];

        // Wx1 preload is pipeline-independent — do it before/while spinning
#pragma unroll
        for (int h = tid; h < 512; h += 256)
            wt[h] = make_float4(Wx1[h], Wx1[512 + h], Wx1[1024 + h], bx1[h]);

        if (tid == 0) {
            while (*(volatile int*)&g_flagV == 0) __nanosleep(64);
        }
        __syncthreads();
        __threadfence();
#pragma unroll
        for (int h = tid; h < 512; h += 256) vs[h] = g_v[h];
        __syncthreads();

        const int h0 = w << 6;            // 64 h per warp
        const int r0 = cid * 128 + lane * 4;

        float xv[12];
        if (r0 + 3 < Bn) {
            const float4* xp = (const float4*)(X + r0 * 3);   // 16B-aligned
#pragma unroll
            for (int qq = 0; qq < 3; qq++) {
                const float4 v4 = xp[qq];
                xv[qq * 4 + 0] = v4.x; xv[qq * 4 + 1] = v4.y;
                xv[qq * 4 + 2] = v4.z; xv[qq * 4 + 3] = v4.w;
            }
        } else {
#pragma unroll
            for (int qq = 0; qq < 12; qq++) {
                const int gi = r0 * 3 + qq;
                xv[qq] = (gi < Bn * 3) ? X[gi] : 0.f;
            }
        }

        float a0 = 0.f, a1 = 0.f, a2 = 0.f, a3 = 0.f;
#pragma unroll 4
        for (int hh = 0; hh < 64; hh += 2) {
            {   // even h: MUFU tanh
                const float4 wv = wt[h0 + hh];
                const float  vv = vs[h0 + hh];
                const float z0 = fmaf(xv[2],  wv.z, fmaf(xv[1],  wv.y, fmaf(xv[0], wv.x, wv.w)));
                const float z1 = fmaf(xv[5],  wv.z, fmaf(xv[4],  wv.y, fmaf(xv[3], wv.x, wv.w)));
                const float z2 = fmaf(xv[8],  wv.z, fmaf(xv[7],  wv.y, fmaf(xv[6], wv.x, wv.w)));
                const float z3 = fmaf(xv[11], wv.z, fmaf(xv[10], wv.y, fmaf(xv[9], wv.x, wv.w)));
                a0 = fmaf(vv, tanh_mufu(z0), a0);
                a1 = fmaf(vv, tanh_mufu(z1), a1);
                a2 = fmaf(vv, tanh_mufu(z2), a2);
                a3 = fmaf(vv, tanh_mufu(z3), a3);
            }
            {   // odd h: fp32 Pade on FMA pipe
                const float4 wv = wt[h0 + hh + 1];
                const float  vv = vs[h0 + hh + 1];
                const float z0 = fmaf(xv[2],  wv.z, fmaf(xv[1],  wv.y, fmaf(xv[0], wv.x, wv.w)));
                const float z1 = fmaf(xv[5],  wv.z, fmaf(xv[4],  wv.y, fmaf(xv[3], wv.x, wv.w)));
                const float z2 = fmaf(xv[8],  wv.z, fmaf(xv[7],  wv.y, fmaf(xv[6], wv.x, wv.w)));
                const float z3 = fmaf(xv[11], wv.z, fmaf(xv[10], wv.y, fmaf(xv[9], wv.x, wv.w)));
                a0 = fmaf(vv, tanh_fma(z0), a0);
                a1 = fmaf(vv, tanh_fma(z1), a1);
                a2 = fmaf(vv, tanh_fma(z2), a2);
                a3 = fmaf(vv, tanh_fma(z3), a3);
            }
        }

        *((float4*)&pp[w][lane * 4]) = make_float4(a0, a1, a2, a3);
        __syncthreads();

        if (tid < 128) {
            float s = g_c;
#pragma unroll
            for (int w2 = 0; w2 < 8; w2++) s += pp[w2][tid];
            const int oi = cid * 128 + tid;
            if (oi < Bn) out[oi] = s;
        }
    }

    // =================== epilogue: reset counters for next replay ========
    __syncthreads();
    if (tid == 0) {
        __threadfence();
        const int d = atomicAdd(&g_cntEnd, 1);
        if (d == (int)gridDim.x - 1) {
            *(volatile int*)&g_cntA   = 0;
            *(volatile int*)&g_cntV   = 0;
            *(volatile int*)&g_flagV  = 0;
            *(volatile int*)&g_cntEnd = 0;
        }
    }
}

// ---------------------------------------------------------------------------
extern "C" void kernel_launch(void* const* d_in, const int* in_sizes, int n_in,
                              void* d_out, int out_size)
{
    const float* input = (const float*)d_in[0];
    const float* eq    = (const float*)d_in[1];
    const float* q0    = (const float*)d_in[2];
    const float* q1    = (const float*)d_in[3];
    const float* q2    = (const float*)d_in[4];
    const float* Wx1   = (const float*)d_in[5];
    const float* bx1   = (const float*)d_in[6];
    const float* Wx2   = (const float*)d_in[7];
    const float* bx2   = (const float*)d_in[8];
    const float* Wq01  = (const float*)d_in[9];
    const float* bq01  = (const float*)d_in[10];
    const float* Wq02  = (const float*)d_in[11];
    const float* bq02  = (const float*)d_in[12];
    const float* Wq11  = (const float*)d_in[13];
    const float* bq11  = (const float*)d_in[14];
    const float* Wq12  = (const float*)d_in[15];
    const float* bq12  = (const float*)d_in[16];
    const float* Wq21  = (const float*)d_in[17];
    const float* bq21  = (const float*)d_in[18];
    const float* Wq22  = (const float*)d_in[19];
    const float* bq22  = (const float*)d_in[20];

    const int Bn   = in_sizes[0] / 3;       // 65536
    const int numC = (Bn + 127) / 128;      // 512
    const int grid = NA + NV + numC;        // 1408

    mega<<<grid, 256>>>(input, eq, q0, q1, q2,
                        Wx1, bx1, Wx2, bx2,
                        Wq01, bq01, Wq02, bq02,
                        Wq11, bq11, Wq12, bq12,
                        Wq21, bq21, Wq22, bq22,
                        (float*)d_out, Bn);
}

// round 12
// speedup vs baseline: 1.4432x; 1.4432x over previous
#include <cuda_runtime.h>

// ---------------------------------------------------------------------------
// DecGreenNet_product_CP3 — algebraically collapsed (R8 structure):
//   out[i] = c + sum_h v[h] * tanh(x_i . Wx1[:,h] + bx1[h])
//   s_br = (sum_n y_n h_n) @ Wq2_br + (sum_n y_n) * bq2_br
//   rhs[b,d,f] = sum_x s0[b,x] s1[d,x] s2[f,x];  v = Wx2 @ rhs;  c = bx2 . rhs
// kernelC: hybrid tanh — even h on MUFU (tanh.approx, rt16), odd h on the
// FMA pipe (fp32 Pade[7/6] + rcp, 8 MUFU-cyc).  Cuts the MUFU ceiling 25%.
// Hybrid precision validated in R11: rel_err 4.4e-6.
// ---------------------------------------------------------------------------

#define PI_F 3.14159265358979323846f

__device__ float g_part[3][128][128];  // per-branch per-chunk weighted-tanh sums
__device__ float g_party[3][128];      // per-branch per-chunk sum of y
__device__ float g_v[512];
__device__ float g_c;

__device__ __forceinline__ float tanh_mufu(float x) {
    float y;
    asm("tanh.approx.f32 %0, %1;" : "=f"(y) : "f"(x));
    return y;
}
__device__ __forceinline__ float frcp(float x) {
    float y;
    asm("rcp.approx.f32 %0, %1;" : "=f"(y) : "f"(x));
    return y;
}
// accurate tanh (~1e-6 abs err) — branch path (cancellation-sensitive sums)
__device__ __forceinline__ float tanh_acc(float z) {
    float e = __expf(2.0f * z);
    return 1.0f - __fdividef(2.0f, e + 1.0f);
}
// fp32 Pade[7/6] tanh on FMA pipe, clamp +-4.97, abs err ~1e-4 (R11-validated)
__device__ __forceinline__ float tanh_fma(float z) {
    const float zc = fminf(fmaxf(z, -4.97f), 4.97f);
    const float t  = zc * zc;
    const float p  = zc * fmaf(t, fmaf(t, t + 378.0f, 17325.0f), 135135.0f);
    const float q  = fmaf(t, fmaf(t, fmaf(t, 28.0f, 3150.0f), 62370.0f), 135135.0f);
    return p * frcp(q);
}

// ---------------------------------------------------------------------------
// Kernel A: branch partials.  grid (128, 3) x 512 threads; chunk = 64 nodes.
// No pre-loop barrier: each warp loads 16 nodes into lanes, broadcasts by shfl.
// ---------------------------------------------------------------------------
__global__ void __launch_bounds__(512) kernelA(
        const float* __restrict__ q0, const float* __restrict__ q1,
        const float* __restrict__ q2,
        const float* __restrict__ w0, const float* __restrict__ w1,
        const float* __restrict__ w2,
        const float* __restrict__ c0, const float* __restrict__ c1,
        const float* __restrict__ c2,
        const float* __restrict__ eq)
{
    const int br = blockIdx.y;
    const float* qx = (br == 0) ? q0 : ((br == 1) ? q1 : q2);
    const float* W1 = (br == 0) ? w0 : ((br == 1) ? w1 : w2);
    const float* B1 = (br == 0) ? c0 : ((br == 1) ? c1 : c2);

    __shared__ float pacc[4][128];
    __shared__ float sy64[64];

    const int t    = threadIdx.x;
    const int lane = t & 31;
    const int w    = t >> 5;          // 0..15
    const int grp  = w >> 2;          // 0..3 -> which 16 nodes
    const int j    = ((w & 3) << 5) + lane;

    const float pe = PI_F * eq[0];

    float q = 0.f, y = 0.f;
    if (lane < 16) {
        q = qx[blockIdx.x * 64 + grp * 16 + lane];
        y = sinf(pe * q);
        if ((w & 3) == 0) sy64[grp * 16 + lane] = y;   // for sum_y only
    }

    const float wj = W1[j];
    const float bj = B1[j];
    float acc = 0.f;
#pragma unroll
    for (int k = 0; k < 16; k++) {
        const float qk = __shfl_sync(0xffffffffu, q, k);
        const float yk = __shfl_sync(0xffffffffu, y, k);
        acc = fmaf(yk, tanh_acc(fmaf(qk, wj, bj)), acc);
    }
    pacc[grp][j] = acc;
    __syncthreads();

    if (t < 128) {
        g_part[br][blockIdx.x][t] =
            pacc[0][t] + pacc[1][t] + pacc[2][t] + pacc[3][t];
    } else if (w == 4) {              // one warp reduces sum_y
        float s = sy64[lane] + sy64[lane + 32];
#pragma unroll
        for (int o = 16; o; o >>= 1) s += __shfl_xor_sync(0xffffffffu, s, o);
        if (lane == 0) g_party[br][blockIdx.x] = s;
    }
}

// ---------------------------------------------------------------------------
// Kernel BV: grid 64 x 512.  Every block redundantly computes the tiny
// phases 1-3 (identical deterministic results), then its own 8 rows of
// v = Wx2 @ rhs.  Keeps the 1MB Wx2 stream spread over 64 SMs.
// ---------------------------------------------------------------------------
__global__ void __launch_bounds__(512) kernelBV(
        const float* __restrict__ Wq02, const float* __restrict__ bq02,
        const float* __restrict__ Wq12, const float* __restrict__ bq12,
        const float* __restrict__ Wq22, const float* __restrict__ bq22,
        const float* __restrict__ bx2,  const float* __restrict__ Wx2)
{
    __shared__ float wh[3][128];
    __shared__ float sumy[3];
    __shared__ float s_sh[3][128];
    __shared__ __align__(16) float rsh[512];
    __shared__ float red[512];

    const int t = threadIdx.x;

    // phase 1: reduce per-chunk partials (128 chunks)
    if (t < 384) {
        const int br = t >> 7, j = t & 127;
        float a = 0.f;
#pragma unroll 16
        for (int blk = 0; blk < 128; blk++) a += g_part[br][blk][j];
        wh[br][j] = a;
    } else if (t < 387) {
        const int br = t - 384;
        float s = 0.f;
#pragma unroll 16
        for (int blk = 0; blk < 128; blk++) s += g_party[br][blk];
        sumy[br] = s;
    }
    __syncthreads();

    // phase 2: s_br = wh_br @ Wq2_br + sumy_br * bq2_br (coalesced columns)
    if (t < 384) {
        const int br = t >> 7, c = t & 127;
        const float* W2 = (br == 0) ? Wq02 : ((br == 1) ? Wq12 : Wq22);
        const float* B2 = (br == 0) ? bq02 : ((br == 1) ? bq12 : bq22);
        float a = sumy[br] * B2[c];
#pragma unroll 16
        for (int j = 0; j < 128; j++) a = fmaf(wh[br][j], W2[j * 128 + c], a);
        s_sh[br][c] = a;                   // c = b*16 + x
    }
    __syncthreads();

    // phase 3: rhs + c
    if (t < 512) {
        const int b = t >> 6, d = (t >> 3) & 7, f = t & 7;
        float r = 0.f;
#pragma unroll
        for (int x = 0; x < 16; x++)
            r += s_sh[0][b * 16 + x] * s_sh[1][d * 16 + x] * s_sh[2][f * 16 + x];
        rsh[t] = r;
        red[t] = bx2[t] * r;
    }
    __syncthreads();
    for (int off = 256; off > 0; off >>= 1) {
        if (t < off) red[t] += red[t + off];
        __syncthreads();
    }
    if (blockIdx.x == 0 && t == 0) g_c = red[0];

    // phase V: 8 rows of v per block (warp per row; warps 8..15 idle)
    const int wp   = t >> 5;
    const int lane = t & 31;
    if (wp < 8) {
        const int h = blockIdx.x * 8 + wp;
        const float4* row4 = (const float4*)(Wx2 + h * 512);
        const float4* r4   = (const float4*)rsh;
        float a = 0.f;
#pragma unroll
        for (int k = lane; k < 128; k += 32) {
            const float4 w = row4[k];
            const float4 r = r4[k];
            a = fmaf(w.x, r.x, fmaf(w.y, r.y, fmaf(w.z, r.z, fmaf(w.w, r.w, a))));
        }
#pragma unroll
        for (int o = 16; o; o >>= 1) a += __shfl_xor_sync(0xffffffffu, a, o);
        if (lane == 0) g_v[h] = a;
    }
}

// ---------------------------------------------------------------------------
// Kernel C: main batch.  256 threads = 8 warps; warp = 64 h (broadcast LDS,
// conflict-free), lane = 4 rows.  Hybrid tanh: even h MUFU, odd h FMA-Pade.
// Grid 512.
// ---------------------------------------------------------------------------
__global__ void __launch_bounds__(256) kernelC(const float* __restrict__ X,
                                               const float* __restrict__ Wx1,
                                               const float* __restrict__ bx1,
                                               float* __restrict__ out, int Bn)
{
    __shared__ float4 wt[512];        // {Wx1[0,h], Wx1[1,h], Wx1[2,h], bx1[h]}
    __shared__ float  vs[512];
    __shared__ __align__(16) float pp[8][128];   // [warp][row-in-block]

    const int t = threadIdx.x;
#pragma unroll
    for (int h = t; h < 512; h += 256) {
        wt[h] = make_float4(Wx1[h], Wx1[512 + h], Wx1[1024 + h], bx1[h]);
        vs[h] = g_v[h];
    }
    __syncthreads();

    const int w    = t >> 5;          // 0..7  (h-split)
    const int lane = t & 31;          // 4 rows per lane
    const int h0   = w << 6;          // 64 h per warp
    const int r0   = blockIdx.x * 128 + lane * 4;

    float xv[12];                     // 4 rows x 3 coords
    if (r0 + 3 < Bn) {
        // r0 multiple of 4 -> byte offset r0*12 is 16B-aligned; 48B contiguous
        const float4* xp = (const float4*)(X + r0 * 3);
#pragma unroll
        for (int q = 0; q < 3; q++) {
            const float4 v4 = xp[q];
            xv[q * 4 + 0] = v4.x; xv[q * 4 + 1] = v4.y;
            xv[q * 4 + 2] = v4.z; xv[q * 4 + 3] = v4.w;
        }
    } else {
#pragma unroll
        for (int q = 0; q < 12; q++) {
            const int gi = r0 * 3 + q;
            xv[q] = (gi < Bn * 3) ? X[gi] : 0.f;
        }
    }

    float a0 = 0.f, a1 = 0.f, a2 = 0.f, a3 = 0.f;
#pragma unroll 4
    for (int hh = 0; hh < 64; hh += 2) {
        {   // even h: MUFU tanh.approx
            const float4 wv = wt[h0 + hh];
            const float  vv = vs[h0 + hh];
            const float z0 = fmaf(xv[2],  wv.z, fmaf(xv[1],  wv.y, fmaf(xv[0], wv.x, wv.w)));
            const float z1 = fmaf(xv[5],  wv.z, fmaf(xv[4],  wv.y, fmaf(xv[3], wv.x, wv.w)));
            const float z2 = fmaf(xv[8],  wv.z, fmaf(xv[7],  wv.y, fmaf(xv[6], wv.x, wv.w)));
            const float z3 = fmaf(xv[11], wv.z, fmaf(xv[10], wv.y, fmaf(xv[9], wv.x, wv.w)));
            a0 = fmaf(vv, tanh_mufu(z0), a0);
            a1 = fmaf(vv, tanh_mufu(z1), a1);
            a2 = fmaf(vv, tanh_mufu(z2), a2);
            a3 = fmaf(vv, tanh_mufu(z3), a3);
        }
        {   // odd h: fp32 Pade on FMA pipe (rcp only touches MUFU)
            const float4 wv = wt[h0 + hh + 1];
            const float  vv = vs[h0 + hh + 1];
            const float z0 = fmaf(xv[2],  wv.z, fmaf(xv[1],  wv.y, fmaf(xv[0], wv.x, wv.w)));
            const float z1 = fmaf(xv[5],  wv.z, fmaf(xv[4],  wv.y, fmaf(xv[3], wv.x, wv.w)));
            const float z2 = fmaf(xv[8],  wv.z, fmaf(xv[7],  wv.y, fmaf(xv[6], wv.x, wv.w)));
            const float z3 = fmaf(xv[11], wv.z, fmaf(xv[10], wv.y, fmaf(xv[9], wv.x, wv.w)));
            a0 = fmaf(vv, tanh_fma(z0), a0);
            a1 = fmaf(vv, tanh_fma(z1), a1);
            a2 = fmaf(vv, tanh_fma(z2), a2);
            a3 = fmaf(vv, tanh_fma(z3), a3);
        }
    }

    // pp[w][lane*4 .. +3]: one conflict-free STS.128 per thread
    *((float4*)&pp[w][lane * 4]) = make_float4(a0, a1, a2, a3);
    __syncthreads();

    if (t < 128) {
        float s = g_c;
#pragma unroll
        for (int w2 = 0; w2 < 8; w2++) s += pp[w2][t];
        const int oi = blockIdx.x * 128 + t;
        if (oi < Bn) out[oi] = s;
    }
}

// ---------------------------------------------------------------------------
extern "C" void kernel_launch(void* const* d_in, const int* in_sizes, int n_in,
                              void* d_out, int out_size)
{
    const float* input = (const float*)d_in[0];
    const float* eq    = (const float*)d_in[1];
    const float* q0    = (const float*)d_in[2];
    const float* q1    = (const float*)d_in[3];
    const float* q2    = (const float*)d_in[4];
    const float* Wx1   = (const float*)d_in[5];
    const float* bx1   = (const float*)d_in[6];
    const float* Wx2   = (const float*)d_in[7];
    const float* bx2   = (const float*)d_in[8];
    const float* Wq01  = (const float*)d_in[9];
    const float* bq01  = (const float*)d_in[10];
    const float* Wq02  = (const float*)d_in[11];
    const float* bq02  = (const float*)d_in[12];
    const float* Wq11  = (const float*)d_in[13];
    const float* bq11  = (const float*)d_in[14];
    const float* Wq12  = (const float*)d_in[15];
    const float* bq12  = (const float*)d_in[16];
    const float* Wq21  = (const float*)d_in[17];
    const float* bq21  = (const float*)d_in[18];
    const float* Wq22  = (const float*)d_in[19];
    const float* bq22  = (const float*)d_in[20];

    const int N  = in_sizes[2];          // 8192 quad nodes
    const int Bn = in_sizes[0] / 3;      // 65536 rows
    const int nblkA = N / 64;            // 128 chunks of 64 nodes

    kernelA<<<dim3(nblkA, 3), 512>>>(q0, q1, q2,
                                     Wq01, Wq11, Wq21,
                                     bq01, bq11, bq21, eq);
    kernelBV<<<64, 512>>>(Wq02, bq02, Wq12, bq12, Wq22, bq22, bx2, Wx2);
    kernelC<<<(Bn + 127) / 128, 256>>>(input, Wx1, bx1, (float*)d_out, Bn);
}

// round 13
// speedup vs baseline: 1.5758x; 1.0919x over previous
#include <cuda_runtime.h>

// ---------------------------------------------------------------------------
// DecGreenNet_product_CP3 — algebraically collapsed:
//   out[i] = c + sum_h v[h] * tanh(x_i . Wx1[:,h] + bx1[h])
//   s_br = (sum_n y_n h_n) @ Wq2_br + (sum_n y_n) * bq2_br
//   rhs[b,d,f] = sum_x s0[b,x] s1[d,x] s2[f,x];  v = Wx2 @ rhs;  c = bx2 . rhs
//
// R13: (1) kernelAV fuses A + BV (448 blocks, all wave-1-resident; BV spins
// on g_cntA — deadlock-free by residency).  (2) kernelC warp-split hybrid:
// warps 0-5 use MUFU tanh.approx; warps 6-7 use Pade[7/6] with an FMA-ONLY
// reciprocal (magic guess + 3 Newton) — zero MUFU.  sm_100a MUFU is rt16 for
// ALL ops (incl. rcp — R12's regression), so only a MUFU-free path helps.
// ---------------------------------------------------------------------------

#define PI_F 3.14159265358979323846f
#define NA_BLK 384          // 3 branches x 128 chunks of 64 nodes
#define NV_BLK 64

__device__ float g_part[3][128][128];  // per-branch per-chunk weighted-tanh sums
__device__ float g_party[3][128];      // per-branch per-chunk sum of y
__device__ float g_v[512];
__device__ float g_c;
__device__ int   g_cntA;
__device__ int   g_cntEnd;

__device__ __forceinline__ float tanh_mufu(float x) {
    float y;
    asm("tanh.approx.f32 %0, %1;" : "=f"(y) : "f"(x));
    return y;
}
// accurate tanh (~1e-6 abs err) — branch path (cancellation-sensitive sums)
__device__ __forceinline__ float tanh_acc(float z) {
    float e = __expf(2.0f * z);
    return 1.0f - __fdividef(2.0f, e + 1.0f);
}
// MUFU-free tanh: Pade[7/6] (R11/R12-validated coefficients) with FMA-only
// reciprocal.  q in [1.35e5, 4.1e6] (positive, normal) -> magic guess
// (rel err <= ~0.13) + 3 Newton steps -> rel err ~1e-7.  abs err ~1e-4.
__device__ __forceinline__ float tanh_nomufu(float z) {
    const float zc = fminf(fmaxf(z, -4.97f), 4.97f);
    const float t  = zc * zc;
    const float p  = zc * fmaf(t, fmaf(t, t + 378.0f, 17325.0f), 135135.0f);
    const float q  = fmaf(t, fmaf(t, fmaf(t, 28.0f, 3150.0f), 62370.0f), 135135.0f);
    float y = __int_as_float(0x7EF311C3 - __float_as_int(q));
    y = y * fmaf(-q, y, 2.0f);
    y = y * fmaf(-q, y, 2.0f);
    y = y * fmaf(-q, y, 2.0f);
    return p * y;
}

// ---------------------------------------------------------------------------
// Kernel AV: 448 blocks x 512 threads, all resident in wave 1 (<= 592 slots).
//   bid 0..383  : A-role — branch partials over 64-node chunks (R8 kernelA)
//   bid 384..447: BV-role — spin on g_cntA, then reduce -> s_br -> rhs -> c,
//                 then 8 rows of v = Wx2 @ rhs per block.
// ---------------------------------------------------------------------------
__global__ void __launch_bounds__(512) kernelAV(
        const float* __restrict__ q0, const float* __restrict__ q1,
        const float* __restrict__ q2,
        const float* __restrict__ w0, const float* __restrict__ w1,
        const float* __restrict__ w2,
        const float* __restrict__ c0, const float* __restrict__ c1,
        const float* __restrict__ c2,
        const float* __restrict__ eq,
        const float* __restrict__ Wq02, const float* __restrict__ bq02,
        const float* __restrict__ Wq12, const float* __restrict__ bq12,
        const float* __restrict__ Wq22, const float* __restrict__ bq22,
        const float* __restrict__ bx2,  const float* __restrict__ Wx2)
{
    const int bid  = blockIdx.x;
    const int t    = threadIdx.x;
    const int lane = t & 31;
    const int w    = t >> 5;          // 0..15

    if (bid < NA_BLK) {
        // ================= A role =================
        const int br    = bid >> 7;       // 0..2
        const int chunk = bid & 127;      // 0..127
        const float* qx = (br == 0) ? q0 : ((br == 1) ? q1 : q2);
        const float* W1 = (br == 0) ? w0 : ((br == 1) ? w1 : w2);
        const float* B1 = (br == 0) ? c0 : ((br == 1) ? c1 : c2);

        __shared__ float pacc[4][128];
        __shared__ float sy64[64];

        const int grp = w >> 2;           // 0..3 -> which 16 nodes
        const int j   = ((w & 3) << 5) + lane;

        const float pe = PI_F * eq[0];
        float q = 0.f, y = 0.f;
        if (lane < 16) {
            q = qx[chunk * 64 + grp * 16 + lane];
            y = sinf(pe * q);
            if ((w & 3) == 0) sy64[grp * 16 + lane] = y;
        }

        const float wj = W1[j];
        const float bj = B1[j];
        float acc = 0.f;
#pragma unroll
        for (int k = 0; k < 16; k++) {
            const float qk = __shfl_sync(0xffffffffu, q, k);
            const float yk = __shfl_sync(0xffffffffu, y, k);
            acc = fmaf(yk, tanh_acc(fmaf(qk, wj, bj)), acc);
        }
        pacc[grp][j] = acc;
        __syncthreads();

        if (t < 128) {
            g_part[br][chunk][t] =
                pacc[0][t] + pacc[1][t] + pacc[2][t] + pacc[3][t];
        } else if (w == 4) {
            float s = sy64[lane] + sy64[lane + 32];
#pragma unroll
            for (int o = 16; o; o >>= 1) s += __shfl_xor_sync(0xffffffffu, s, o);
            if (lane == 0) g_party[br][chunk] = s;
        }
        __syncthreads();
        __threadfence();
        if (t == 0) atomicAdd(&g_cntA, 1);
    } else {
        // ================= BV role =================
        const int vid = bid - NA_BLK;     // 0..63

        __shared__ float wh[3][128];
        __shared__ float sumy[3];
        __shared__ float s_sh[3][128];
        __shared__ __align__(16) float rsh[512];
        __shared__ float red[512];

        // L2-prefetch this block's 8 Wx2 rows while A runs
        {
            const float* base = Wx2 + (vid * 8) * 512;
            for (int off = t * 32; off < 8 * 512; off += 512 * 32)
                asm volatile("prefetch.global.L2 [%0];" :: "l"(base + off));
        }
        if (t == 0) {
            while (*(volatile int*)&g_cntA != NA_BLK) __nanosleep(64);
        }
        __syncthreads();
        __threadfence();

        // phase 1: reduce per-chunk partials
        if (t < 384) {
            const int br = t >> 7, j = t & 127;
            float a = 0.f;
#pragma unroll 16
            for (int blk = 0; blk < 128; blk++) a += g_part[br][blk][j];
            wh[br][j] = a;
        } else if (t < 387) {
            const int br = t - 384;
            float s = 0.f;
#pragma unroll 16
            for (int blk = 0; blk < 128; blk++) s += g_party[br][blk];
            sumy[br] = s;
        }
        __syncthreads();

        // phase 2: s_br = wh_br @ Wq2_br + sumy_br * bq2_br
        if (t < 384) {
            const int br = t >> 7, c = t & 127;
            const float* W2 = (br == 0) ? Wq02 : ((br == 1) ? Wq12 : Wq22);
            const float* B2 = (br == 0) ? bq02 : ((br == 1) ? bq12 : bq22);
            float a = sumy[br] * B2[c];
#pragma unroll 16
            for (int j = 0; j < 128; j++) a = fmaf(wh[br][j], W2[j * 128 + c], a);
            s_sh[br][c] = a;              // c = b*16 + x
        }
        __syncthreads();

        // phase 3: rhs + c
        {
            const int b = t >> 6, d = (t >> 3) & 7, f = t & 7;
            float r = 0.f;
#pragma unroll
            for (int x = 0; x < 16; x++)
                r += s_sh[0][b * 16 + x] * s_sh[1][d * 16 + x] * s_sh[2][f * 16 + x];
            rsh[t] = r;
            red[t] = bx2[t] * r;
        }
        __syncthreads();
        for (int off = 256; off > 0; off >>= 1) {
            if (t < off) red[t] += red[t + off];
            __syncthreads();
        }
        if (vid == 0 && t == 0) g_c = red[0];

        // phase V: 8 rows of v per block (warp per row; warps 8..15 idle)
        if (w < 8) {
            const int h = vid * 8 + w;
            const float4* row4 = (const float4*)(Wx2 + h * 512);
            const float4* r4   = (const float4*)rsh;
            float a = 0.f;
#pragma unroll
            for (int k = lane; k < 128; k += 32) {
                const float4 wv = row4[k];
                const float4 rv = r4[k];
                a = fmaf(wv.x, rv.x, fmaf(wv.y, rv.y,
                    fmaf(wv.z, rv.z, fmaf(wv.w, rv.w, a))));
            }
#pragma unroll
            for (int o = 16; o; o >>= 1) a += __shfl_xor_sync(0xffffffffu, a, o);
            if (lane == 0) g_v[h] = a;
        }
    }

    // epilogue: last block resets counters for the next graph replay
    __syncthreads();
    if (t == 0) {
        __threadfence();
        const int d = atomicAdd(&g_cntEnd, 1);
        if (d == (int)gridDim.x - 1) {
            *(volatile int*)&g_cntA   = 0;
            *(volatile int*)&g_cntEnd = 0;
        }
    }
}

// ---------------------------------------------------------------------------
// Kernel C: main batch.  256 threads = 8 warps; warp = 64 h (broadcast LDS,
// conflict-free), lane = 4 rows.  WARP-SPLIT hybrid: warps 0-5 use MUFU
// tanh.approx; warps 6-7 use the MUFU-free Pade path.  Each warp's body is
// uniform and small.  MUFU demand drops 16 -> 12 cyc/tanh average.
// ---------------------------------------------------------------------------
__global__ void __launch_bounds__(256) kernelC(const float* __restrict__ X,
                                               const float* __restrict__ Wx1,
                                               const float* __restrict__ bx1,
                                               float* __restrict__ out, int Bn)
{
    __shared__ float4 wt[512];        // {Wx1[0,h], Wx1[1,h], Wx1[2,h], bx1[h]}
    __shared__ float  vs[512];
    __shared__ __align__(16) float pp[8][128];   // [warp][row-in-block]

    const int t = threadIdx.x;
#pragma unroll
    for (int h = t; h < 512; h += 256) {
        wt[h] = make_float4(Wx1[h], Wx1[512 + h], Wx1[1024 + h], bx1[h]);
        vs[h] = g_v[h];
    }
    __syncthreads();

    const int w    = t >> 5;          // 0..7  (h-split)
    const int lane = t & 31;          // 4 rows per lane
    const int h0   = w << 6;          // 64 h per warp
    const int r0   = blockIdx.x * 128 + lane * 4;

    float xv[12];                     // 4 rows x 3 coords
    if (r0 + 3 < Bn) {
        const float4* xp = (const float4*)(X + r0 * 3);   // 16B-aligned
#pragma unroll
        for (int q = 0; q < 3; q++) {
            const float4 v4 = xp[q];
            xv[q * 4 + 0] = v4.x; xv[q * 4 + 1] = v4.y;
            xv[q * 4 + 2] = v4.z; xv[q * 4 + 3] = v4.w;
        }
    } else {
#pragma unroll
        for (int q = 0; q < 12; q++) {
            const int gi = r0 * 3 + q;
            xv[q] = (gi < Bn * 3) ? X[gi] : 0.f;
        }
    }

    float a0 = 0.f, a1 = 0.f, a2 = 0.f, a3 = 0.f;

    if (w < 6) {
        // ---- MUFU warps ----
#pragma unroll 8
        for (int hh = 0; hh < 64; hh++) {
            const float4 wv = wt[h0 + hh];    // warp-uniform: broadcast
            const float  vv = vs[h0 + hh];
            const float z0 = fmaf(xv[2],  wv.z, fmaf(xv[1],  wv.y, fmaf(xv[0], wv.x, wv.w)));
            const float z1 = fmaf(xv[5],  wv.z, fmaf(xv[4],  wv.y, fmaf(xv[3], wv.x, wv.w)));
            const float z2 = fmaf(xv[8],  wv.z, fmaf(xv[7],  wv.y, fmaf(xv[6], wv.x, wv.w)));
            const float z3 = fmaf(xv[11], wv.z, fmaf(xv[10], wv.y, fmaf(xv[9], wv.x, wv.w)));
            a0 = fmaf(vv, tanh_mufu(z0), a0);
            a1 = fmaf(vv, tanh_mufu(z1), a1);
            a2 = fmaf(vv, tanh_mufu(z2), a2);
            a3 = fmaf(vv, tanh_mufu(z3), a3);
        }
    } else {
        // ---- MUFU-free warps (FMA pipe) ----
#pragma unroll 4
        for (int hh = 0; hh < 64; hh++) {
            const float4 wv = wt[h0 + hh];
            const float  vv = vs[h0 + hh];
            const float z0 = fmaf(xv[2],  wv.z, fmaf(xv[1],  wv.y, fmaf(xv[0], wv.x, wv.w)));
            const float z1 = fmaf(xv[5],  wv.z, fmaf(xv[4],  wv.y, fmaf(xv[3], wv.x, wv.w)));
            const float z2 = fmaf(xv[8],  wv.z, fmaf(xv[7],  wv.y, fmaf(xv[6], wv.x, wv.w)));
            const float z3 = fmaf(xv[11], wv.z, fmaf(xv[10], wv.y, fmaf(xv[9], wv.x, wv.w)));
            a0 = fmaf(vv, tanh_nomufu(z0), a0);
            a1 = fmaf(vv, tanh_nomufu(z1), a1);
            a2 = fmaf(vv, tanh_nomufu(z2), a2);
            a3 = fmaf(vv, tanh_nomufu(z3), a3);
        }
    }

    *((float4*)&pp[w][lane * 4]) = make_float4(a0, a1, a2, a3);
    __syncthreads();

    if (t < 128) {
        float s = g_c;
#pragma unroll
        for (int w2 = 0; w2 < 8; w2++) s += pp[w2][t];
        const int oi = blockIdx.x * 128 + t;
        if (oi < Bn) out[oi] = s;
    }
}

// ---------------------------------------------------------------------------
extern "C" void kernel_launch(void* const* d_in, const int* in_sizes, int n_in,
                              void* d_out, int out_size)
{
    const float* input = (const float*)d_in[0];
    const float* eq    = (const float*)d_in[1];
    const float* q0    = (const float*)d_in[2];
    const float* q1    = (const float*)d_in[3];
    const float* q2    = (const float*)d_in[4];
    const float* Wx1   = (const float*)d_in[5];
    const float* bx1   = (const float*)d_in[6];
    const float* Wx2   = (const float*)d_in[7];
    const float* bx2   = (const float*)d_in[8];
    const float* Wq01  = (const float*)d_in[9];
    const float* bq01  = (const float*)d_in[10];
    const float* Wq02  = (const float*)d_in[11];
    const float* bq02  = (const float*)d_in[12];
    const float* Wq11  = (const float*)d_in[13];
    const float* bq11  = (const float*)d_in[14];
    const float* Wq12  = (const float*)d_in[15];
    const float* bq12  = (const float*)d_in[16];
    const float* Wq21  = (const float*)d_in[17];
    const float* bq21  = (const float*)d_in[18];
    const float* Wq22  = (const float*)d_in[19];
    const float* bq22  = (const float*)d_in[20];

    const int Bn = in_sizes[0] / 3;      // 65536 rows

    kernelAV<<<NA_BLK + NV_BLK, 512>>>(q0, q1, q2,
                                       Wq01, Wq11, Wq21,
                                       bq01, bq11, bq21, eq,
                                       Wq02, bq02, Wq12, bq12, Wq22, bq22,
                                       bx2, Wx2);
    kernelC<<<(Bn + 127) / 128, 256>>>(input, Wx1, bx1, (float*)d_out, Bn);
}

// round 14
// speedup vs baseline: 1.7279x; 1.0966x over previous
#include <cuda_runtime.h>

// ---------------------------------------------------------------------------
// DecGreenNet_product_CP3 — algebraically collapsed:
//   out[i] = c + sum_h v[h] * tanh(x_i . Wx1[:,h] + bx1[h])
//   s_br = (sum_n y_n h_n) @ Wq2_br + (sum_n y_n) * bq2_br
//   rhs[b,d,f] = sum_x s0[b,x] s1[d,x] s2[f,x];  v = Wx2 @ rhs;  c = bx2 . rhs
//
// R14 = proven pieces only:
//   kernelAV : R13 fusion (A + BV, all wave-1-resident, flag-synced), with
//              A's tanh using ONE MUFU op (exp) + FMA-Newton reciprocal
//              (was exp + rcp = 2 MUFU) -> halves A's MUFU demand.
//   kernelC  : R8 pure-MUFU version verbatim (13.5us, at the rt16 ceiling;
//              all hybrid variants regressed — abandoned).
// ---------------------------------------------------------------------------

#define PI_F 3.14159265358979323846f
#define NA_BLK 384          // 3 branches x 128 chunks of 64 nodes
#define NV_BLK 64

__device__ float g_part[3][128][128];  // per-branch per-chunk weighted-tanh sums
__device__ float g_party[3][128];      // per-branch per-chunk sum of y
__device__ float g_v[512];
__device__ float g_c;
__device__ int   g_cntA;
__device__ int   g_cntEnd;

__device__ __forceinline__ float tanh_mufu(float x) {
    float y;
    asm("tanh.approx.f32 %0, %1;" : "=f"(y) : "f"(x));
    return y;
}
// accurate tanh (~1e-7..1e-6 abs err) with ONE MUFU op:
//   tanh(z) = 1 - 2/(e^{2z}+1);  reciprocal via magic guess + 3 Newton (FMA).
//   d = e^{2z}+1 in [1, ~2.2e4]: positive, normal -> Newton converges, err^8.
__device__ __forceinline__ float tanh_acc(float z) {
    const float d = __expf(2.0f * z) + 1.0f;      // 1 MUFU (ex2) + fma
    float y = __int_as_float(0x7EF311C3 - __float_as_int(d));
    y = y * fmaf(-d, y, 2.0f);
    y = y * fmaf(-d, y, 2.0f);
    y = y * fmaf(-d, y, 2.0f);
    return fmaf(-2.0f, y, 1.0f);
}

// ---------------------------------------------------------------------------
// Kernel AV: 448 blocks x 512 threads, all resident in wave 1 (<= 592 slots).
//   bid 0..383  : A-role — branch partials over 64-node chunks
//   bid 384..447: BV-role — spin on g_cntA, then reduce -> s_br -> rhs -> c,
//                 then 8 rows of v = Wx2 @ rhs per block.
// (Structure validated in R13: passed, rel_err 4.4e-6.)
// ---------------------------------------------------------------------------
__global__ void __launch_bounds__(512) kernelAV(
        const float* __restrict__ q0, const float* __restrict__ q1,
        const float* __restrict__ q2,
        const float* __restrict__ w0, const float* __restrict__ w1,
        const float* __restrict__ w2,
        const float* __restrict__ c0, const float* __restrict__ c1,
        const float* __restrict__ c2,
        const float* __restrict__ eq,
        const float* __restrict__ Wq02, const float* __restrict__ bq02,
        const float* __restrict__ Wq12, const float* __restrict__ bq12,
        const float* __restrict__ Wq22, const float* __restrict__ bq22,
        const float* __restrict__ bx2,  const float* __restrict__ Wx2)
{
    const int bid  = blockIdx.x;
    const int t    = threadIdx.x;
    const int lane = t & 31;
    const int w    = t >> 5;          // 0..15

    if (bid < NA_BLK) {
        // ================= A role =================
        const int br    = bid >> 7;       // 0..2
        const int chunk = bid & 127;      // 0..127
        const float* qx = (br == 0) ? q0 : ((br == 1) ? q1 : q2);
        const float* W1 = (br == 0) ? w0 : ((br == 1) ? w1 : w2);
        const float* B1 = (br == 0) ? c0 : ((br == 1) ? c1 : c2);

        __shared__ float pacc[4][128];
        __shared__ float sy64[64];

        const int grp = w >> 2;           // 0..3 -> which 16 nodes
        const int j   = ((w & 3) << 5) + lane;

        const float pe = PI_F * eq[0];
        float q = 0.f, y = 0.f;
        if (lane < 16) {
            q = qx[chunk * 64 + grp * 16 + lane];
            y = sinf(pe * q);
            if ((w & 3) == 0) sy64[grp * 16 + lane] = y;
        }

        const float wj = W1[j];
        const float bj = B1[j];
        float acc0 = 0.f, acc1 = 0.f;     // 2 chains for ILP
#pragma unroll
        for (int k = 0; k < 16; k += 2) {
            const float qa = __shfl_sync(0xffffffffu, q, k);
            const float ya = __shfl_sync(0xffffffffu, y, k);
            const float qb = __shfl_sync(0xffffffffu, q, k + 1);
            const float yb = __shfl_sync(0xffffffffu, y, k + 1);
            acc0 = fmaf(ya, tanh_acc(fmaf(qa, wj, bj)), acc0);
            acc1 = fmaf(yb, tanh_acc(fmaf(qb, wj, bj)), acc1);
        }
        pacc[grp][j] = acc0 + acc1;
        __syncthreads();

        if (t < 128) {
            g_part[br][chunk][t] =
                pacc[0][t] + pacc[1][t] + pacc[2][t] + pacc[3][t];
        } else if (w == 4) {
            float s = sy64[lane] + sy64[lane + 32];
#pragma unroll
            for (int o = 16; o; o >>= 1) s += __shfl_xor_sync(0xffffffffu, s, o);
            if (lane == 0) g_party[br][chunk] = s;
        }
        __syncthreads();
        __threadfence();
        if (t == 0) atomicAdd(&g_cntA, 1);
    } else {
        // ================= BV role =================
        const int vid = bid - NA_BLK;     // 0..63

        __shared__ float wh[3][128];
        __shared__ float sumy[3];
        __shared__ float s_sh[3][128];
        __shared__ __align__(16) float rsh[512];
        __shared__ float red[512];

        // L2-prefetch this block's 8 Wx2 rows while A runs
        {
            const float* base = Wx2 + (vid * 8) * 512;
            for (int off = t * 32; off < 8 * 512; off += 512 * 32)
                asm volatile("prefetch.global.L2 [%0];" :: "l"(base + off));
        }
        if (t == 0) {
            while (*(volatile int*)&g_cntA != NA_BLK) __nanosleep(64);
        }
        __syncthreads();
        __threadfence();

        // phase 1: reduce per-chunk partials
        if (t < 384) {
            const int br = t >> 7, j = t & 127;
            float a = 0.f;
#pragma unroll 16
            for (int blk = 0; blk < 128; blk++) a += g_part[br][blk][j];
            wh[br][j] = a;
        } else if (t < 387) {
            const int br = t - 384;
            float s = 0.f;
#pragma unroll 16
            for (int blk = 0; blk < 128; blk++) s += g_party[br][blk];
            sumy[br] = s;
        }
        __syncthreads();

        // phase 2: s_br = wh_br @ Wq2_br + sumy_br * bq2_br
        if (t < 384) {
            const int br = t >> 7, c = t & 127;
            const float* W2 = (br == 0) ? Wq02 : ((br == 1) ? Wq12 : Wq22);
            const float* B2 = (br == 0) ? bq02 : ((br == 1) ? bq12 : bq22);
            float a = sumy[br] * B2[c];
#pragma unroll 16
            for (int j = 0; j < 128; j++) a = fmaf(wh[br][j], W2[j * 128 + c], a);
            s_sh[br][c] = a;              // c = b*16 + x
        }
        __syncthreads();

        // phase 3: rhs + c
        {
            const int b = t >> 6, d = (t >> 3) & 7, f = t & 7;
            float r = 0.f;
#pragma unroll
            for (int x = 0; x < 16; x++)
                r += s_sh[0][b * 16 + x] * s_sh[1][d * 16 + x] * s_sh[2][f * 16 + x];
            rsh[t] = r;
            red[t] = bx2[t] * r;
        }
        __syncthreads();
        for (int off = 256; off > 0; off >>= 1) {
            if (t < off) red[t] += red[t + off];
            __syncthreads();
        }
        if (vid == 0 && t == 0) g_c = red[0];

        // phase V: 8 rows of v per block (warp per row; warps 8..15 idle)
        if (w < 8) {
            const int h = vid * 8 + w;
            const float4* row4 = (const float4*)(Wx2 + h * 512);
            const float4* r4   = (const float4*)rsh;
            float a = 0.f;
#pragma unroll
            for (int k = lane; k < 128; k += 32) {
                const float4 wv = row4[k];
                const float4 rv = r4[k];
                a = fmaf(wv.x, rv.x, fmaf(wv.y, rv.y,
                    fmaf(wv.z, rv.z, fmaf(wv.w, rv.w, a))));
            }
#pragma unroll
            for (int o = 16; o; o >>= 1) a += __shfl_xor_sync(0xffffffffu, a, o);
            if (lane == 0) g_v[h] = a;
        }
    }

    // epilogue: last block resets counters for the next graph replay
    __syncthreads();
    if (t == 0) {
        __threadfence();
        const int d = atomicAdd(&g_cntEnd, 1);
        if (d == (int)gridDim.x - 1) {
            *(volatile int*)&g_cntA   = 0;
            *(volatile int*)&g_cntEnd = 0;
        }
    }
}

// ---------------------------------------------------------------------------
// Kernel C: main batch (R8 pure-MUFU version, verbatim).  256 threads =
// 8 warps; warp = 64 h (broadcast LDS, conflict-free), lane = 4 rows.
// At the tanh.approx rt16 MUFU ceiling (~13.5us) — proven optimal mapping.
// ---------------------------------------------------------------------------
__global__ void __launch_bounds__(256) kernelC(const float* __restrict__ X,
                                               const float* __restrict__ Wx1,
                                               const float* __restrict__ bx1,
                                               float* __restrict__ out, int Bn)
{
    __shared__ float4 wt[512];        // {Wx1[0,h], Wx1[1,h], Wx1[2,h], bx1[h]}
    __shared__ float  vs[512];
    __shared__ __align__(16) float pp[8][128];   // [warp][row-in-block]

    const int t = threadIdx.x;
#pragma unroll
    for (int h = t; h < 512; h += 256) {
        wt[h] = make_float4(Wx1[h], Wx1[512 + h], Wx1[1024 + h], bx1[h]);
        vs[h] = g_v[h];
    }
    __syncthreads();

    const int w    = t >> 5;          // 0..7  (h-split)
    const int lane = t & 31;          // 4 rows per lane
    const int h0   = w << 6;          // 64 h per warp
    const int r0   = blockIdx.x * 128 + lane * 4;

    float xv[12];                     // 4 rows x 3 coords
    if (r0 + 3 < Bn) {
        const float4* xp = (const float4*)(X + r0 * 3);   // 16B-aligned
#pragma unroll
        for (int q = 0; q < 3; q++) {
            const float4 v4 = xp[q];
            xv[q * 4 + 0] = v4.x; xv[q * 4 + 1] = v4.y;
            xv[q * 4 + 2] = v4.z; xv[q * 4 + 3] = v4.w;
        }
    } else {
#pragma unroll
        for (int q = 0; q < 12; q++) {
            const int gi = r0 * 3 + q;
            xv[q] = (gi < Bn * 3) ? X[gi] : 0.f;
        }
    }

    float a0 = 0.f, a1 = 0.f, a2 = 0.f, a3 = 0.f;
#pragma unroll 8
    for (int hh = 0; hh < 64; hh++) {
        const float4 wv = wt[h0 + hh];    // warp-uniform: broadcast
        const float  vv = vs[h0 + hh];    // broadcast
        const float z0 = fmaf(xv[2],  wv.z, fmaf(xv[1],  wv.y, fmaf(xv[0], wv.x, wv.w)));
        const float z1 = fmaf(xv[5],  wv.z, fmaf(xv[4],  wv.y, fmaf(xv[3], wv.x, wv.w)));
        const float z2 = fmaf(xv[8],  wv.z, fmaf(xv[7],  wv.y, fmaf(xv[6], wv.x, wv.w)));
        const float z3 = fmaf(xv[11], wv.z, fmaf(xv[10], wv.y, fmaf(xv[9], wv.x, wv.w)));
        a0 = fmaf(vv, tanh_mufu(z0), a0);
        a1 = fmaf(vv, tanh_mufu(z1), a1);
        a2 = fmaf(vv, tanh_mufu(z2), a2);
        a3 = fmaf(vv, tanh_mufu(z3), a3);
    }

    // pp[w][lane*4 .. +3]: one conflict-free STS.128 per thread
    *((float4*)&pp[w][lane * 4]) = make_float4(a0, a1, a2, a3);
    __syncthreads();

    if (t < 128) {
        float s = g_c;
#pragma unroll
        for (int w2 = 0; w2 < 8; w2++) s += pp[w2][t];
        const int oi = blockIdx.x * 128 + t;
        if (oi < Bn) out[oi] = s;
    }
}

// ---------------------------------------------------------------------------
extern "C" void kernel_launch(void* const* d_in, const int* in_sizes, int n_in,
                              void* d_out, int out_size)
{
    const float* input = (const float*)d_in[0];
    const float* eq    = (const float*)d_in[1];
    const float* q0    = (const float*)d_in[2];
    const float* q1    = (const float*)d_in[3];
    const float* q2    = (const float*)d_in[4];
    const float* Wx1   = (const float*)d_in[5];
    const float* bx1   = (const float*)d_in[6];
    const float* Wx2   = (const float*)d_in[7];
    const float* bx2   = (const float*)d_in[8];
    const float* Wq01  = (const float*)d_in[9];
    const float* bq01  = (const float*)d_in[10];
    const float* Wq02  = (const float*)d_in[11];
    const float* bq02  = (const float*)d_in[12];
    const float* Wq11  = (const float*)d_in[13];
    const float* bq11  = (const float*)d_in[14];
    const float* Wq12  = (const float*)d_in[15];
    const float* bq12  = (const float*)d_in[16];
    const float* Wq21  = (const float*)d_in[17];
    const float* bq21  = (const float*)d_in[18];
    const float* Wq22  = (const float*)d_in[19];
    const float* bq22  = (const float*)d_in[20];

    const int Bn = in_sizes[0] / 3;      // 65536 rows

    kernelAV<<<NA_BLK + NV_BLK, 512>>>(q0, q1, q2,
                                       Wq01, Wq11, Wq21,
                                       bq01, bq11, bq21, eq,
                                       Wq02, bq02, Wq12, bq12, Wq22, bq22,
                                       bx2, Wx2);
    kernelC<<<(Bn + 127) / 128, 256>>>(input, Wx1, bx1, (float*)d_out, Bn);
}